// round 7
// baseline (speedup 1.0000x reference)
#include <cuda_runtime.h>
#include <cstdint>

#define L_SEQ 1024
#define C_S   1024
#define DD    32      // inner dim
#define CZ    128     // pairwise dim
#define I_PER_CTA 8
#define JT    64      // j columns per phase2 CTA
#define PAD   132     // stage row stride (floats): PAD%32==4 -> conflict-free
#define R1    4       // rows per CTA in phase1

// Scratch (allocation-free rule: __device__ globals)
__device__ float g_q[L_SEQ * DD];
__device__ float g_k[L_SEQ * DD];
__device__ float g_Ak[L_SEQ * CZ];

__device__ __forceinline__ unsigned f2tf(float f) {
    unsigned r;
    asm("cvt.rna.tf32.f32 %0, %1;" : "=r"(r) : "f"(f));
    return r;
}

// ---------------------------------------------------------------------------
// Phase 1: LayerNorm + projection -> q,k [L,32]; Ak[i,z] = sum_d k[i,d]*W2[z,d]
// Grid (L/R1, 2): blockIdx.y selects the d-half (0 -> q, 1 -> k + Ak).
// ---------------------------------------------------------------------------
__global__ __launch_bounds__(256) void phase1_kernel(
    const float* __restrict__ x,
    const float* __restrict__ lnw, const float* __restrict__ lnb,
    const float* __restrict__ pw,  const float* __restrict__ pb,
    const float* __restrict__ ow)
{
    __shared__ float4 s4[R1][C_S / 4];   // 16KB normalized rows
    __shared__ float red[2][R1][8];
    __shared__ float qk[R1][DD];         // this half's 32 outputs per row

    const int tid  = threadIdx.x;
    const int lane = tid & 31;
    const int wid  = tid >> 5;
    const int row0 = blockIdx.x * R1;
    const int h    = blockIdx.y;         // 0: q half, 1: k half

    // ---- LayerNorm for 4 rows ----
    {
        float4 xv[R1];
        float sum[R1], sq[R1];
#pragma unroll
        for (int r = 0; r < R1; r++) {
            xv[r]  = ((const float4*)(x + (size_t)(row0 + r) * C_S))[tid];
            sum[r] = xv[r].x + xv[r].y + xv[r].z + xv[r].w;
            sq[r]  = fmaf(xv[r].x, xv[r].x, fmaf(xv[r].y, xv[r].y,
                     fmaf(xv[r].z, xv[r].z, xv[r].w * xv[r].w)));
        }
#pragma unroll
        for (int o = 16; o; o >>= 1) {
#pragma unroll
            for (int r = 0; r < R1; r++) {
                sum[r] += __shfl_xor_sync(~0u, sum[r], o);
                sq[r]  += __shfl_xor_sync(~0u, sq[r],  o);
            }
        }
        if (lane == 0) {
#pragma unroll
            for (int r = 0; r < R1; r++) { red[0][r][wid] = sum[r]; red[1][r][wid] = sq[r]; }
        }
        __syncthreads();

        const float4 wv = ((const float4*)lnw)[tid];
        const float4 bv = ((const float4*)lnb)[tid];
#pragma unroll
        for (int r = 0; r < R1; r++) {
            float s = 0.f, q = 0.f;
#pragma unroll
            for (int w = 0; w < 8; w++) { s += red[0][r][w]; q += red[1][r][w]; }
            const float mu   = s * (1.0f / C_S);
            const float var  = q * (1.0f / C_S) - mu * mu;
            const float rstd = rsqrtf(var + 1e-5f);
            float4 sv;
            sv.x = (xv[r].x - mu) * rstd * wv.x + bv.x;
            sv.y = (xv[r].y - mu) * rstd * wv.y + bv.y;
            sv.z = (xv[r].z - mu) * rstd * wv.z + bv.z;
            sv.w = (xv[r].w - mu) * rstd * wv.w + bv.w;
            s4[r][tid] = sv;
        }
    }
    __syncthreads();

    // ---- projection: warp w computes local d = w*4 .. w*4+3 for 4 rows ----
#pragma unroll
    for (int rr = 0; rr < 4; rr++) {
        const int dl = wid * 4 + rr;
        const int dg = h * DD + dl;
        const float4* wr = (const float4*)(pw + (size_t)dg * C_S);
        float acc[R1];
#pragma unroll
        for (int r = 0; r < R1; r++) acc[r] = 0.f;
        for (int c = lane; c < C_S / 4; c += 32) {
            const float4 w4 = wr[c];
#pragma unroll
            for (int r = 0; r < R1; r++) {
                const float4 v = s4[r][c];
                acc[r] = fmaf(v.x, w4.x, fmaf(v.y, w4.y,
                         fmaf(v.z, w4.z, fmaf(v.w, w4.w, acc[r]))));
            }
        }
#pragma unroll
        for (int o = 16; o; o >>= 1) {
#pragma unroll
            for (int r = 0; r < R1; r++) acc[r] += __shfl_xor_sync(~0u, acc[r], o);
        }
        if (lane == 0) {
            const float pbd = pb[dg];
#pragma unroll
            for (int r = 0; r < R1; r++) qk[r][dl] = acc[r] + pbd;
        }
    }
    __syncthreads();

    // ---- write q or k ----
    if (tid < R1 * DD) {
        const int r = tid >> 5, v = tid & 31;
        if (h == 0) g_q[(row0 + r) * DD + v] = qk[r][v];
        else        g_k[(row0 + r) * DD + v] = qk[r][v];
    }

    // ---- Ak (k half only): Ak[i,z] = sum_d k[i,d] * W2[z,d] ----
    if (h == 1) {
#pragma unroll
        for (int hh = 0; hh < 2; hh++) {
            const int idx = tid + 256 * hh;
            const int r = idx >> 7, z = idx & 127;
            float acc = 0.f;
#pragma unroll
            for (int d = 0; d < DD; d++)
                acc = fmaf(qk[r][d], __ldg(ow + z * (2 * DD) + DD + d), acc);
            g_Ak[(row0 + r) * CZ + z] = acc;
        }
    }
}

// ---------------------------------------------------------------------------
// Phase 2 (transposed operands): out[i, j, z], M-dim = z, N-dim = j.
//   A[z,d] = Ghat_i[d,z] = k[i,d]*W1[z,d] + W2[z,d]   (built in regs per i)
//   B[d,j] = q[j,d]                                     (regs, CTA-constant)
//   C[z,j] seeded with bias[z] = ob[z] - Ak[i,z]        (2 regs per i)
// Warp w owns z-tile [16w,16w+16) x 64 j. Epilogue via CTA stage[64j][PAD],
// double-buffered, one __syncthreads per i, full-line coalesced drain.
// ---------------------------------------------------------------------------
extern __shared__ char smem_dyn[];

__global__ __launch_bounds__(256, 2) void phase2_kernel(
    const float* __restrict__ ow, const float* __restrict__ ob,
    float* __restrict__ out)
{
    float* stage = (float*)smem_dyn;   // 2 buffers of JT*PAD floats

    const int tid  = threadIdx.x;
    const int lane = tid & 31;
    const int wid  = tid >> 5;
    const int l4   = lane & 3;
    const int lg   = lane >> 2;
    const int jbase = blockIdx.x * JT;
    const int ibase = blockIdx.y * I_PER_CTA;

    const int z0 = wid * 16 + lg;      // accumulator row (z), +8 for upper

    // ---- W1/W2 A-side fragment values, register resident ----
    float w1[4][4], w2[4][4];
#pragma unroll
    for (int kk = 0; kk < 4; kk++) {
        const int d0 = l4 + 8 * kk;
        w1[kk][0] = ow[z0 * (2 * DD) + d0];
        w1[kk][1] = ow[(z0 + 8) * (2 * DD) + d0];
        w1[kk][2] = ow[z0 * (2 * DD) + d0 + 4];
        w1[kk][3] = ow[(z0 + 8) * (2 * DD) + d0 + 4];
        w2[kk][0] = ow[z0 * (2 * DD) + DD + d0];
        w2[kk][1] = ow[(z0 + 8) * (2 * DD) + DD + d0];
        w2[kk][2] = ow[z0 * (2 * DD) + DD + d0 + 4];
        w2[kk][3] = ow[(z0 + 8) * (2 * DD) + DD + d0 + 4];
    }

    // ---- q B-side fragments: constant for whole CTA ----
    unsigned bq0[8][4], bq1[8][4];
#pragma unroll
    for (int n = 0; n < 8; n++) {
        const int j = jbase + 8 * n + lg;
#pragma unroll
        for (int kk = 0; kk < 4; kk++) {
            const int d0 = l4 + 8 * kk;
            bq0[n][kk] = f2tf(g_q[j * DD + d0]);
            bq1[n][kk] = f2tf(g_q[j * DD + d0 + 4]);
        }
    }

    const float ob0 = ob[z0];
    const float ob1 = ob[z0 + 8];

    // drain indices (fixed per thread)
    const int dj = tid >> 3;            // 0..31
    const int dz = (tid & 7) * 4;       // 0..28

    for (int ii = 0; ii < I_PER_CTA; ii++) {
        const int i = ibase + ii;
        float* stg = stage + (ii & 1) * (JT * PAD);

        const float bias0 = ob0 - g_Ak[i * CZ + z0];
        const float bias1 = ob1 - g_Ak[i * CZ + z0 + 8];

        // build A fragments for this i (16 FMA + 16 CVT, no smem)
        unsigned afr[4][4];
#pragma unroll
        for (int kk = 0; kk < 4; kk++) {
            const int d0 = l4 + 8 * kk;
            const float k0 = g_k[i * DD + d0];
            const float k1 = g_k[i * DD + d0 + 4];
            afr[kk][0] = f2tf(fmaf(k0, w1[kk][0], w2[kk][0]));
            afr[kk][1] = f2tf(fmaf(k0, w1[kk][1], w2[kk][1]));
            afr[kk][2] = f2tf(fmaf(k1, w1[kk][2], w2[kk][2]));
            afr[kk][3] = f2tf(fmaf(k1, w1[kk][3], w2[kk][3]));
        }

        float* sbase = stg + (2 * l4) * PAD + z0;
#pragma unroll
        for (int n = 0; n < 8; n++) {
            float c0 = bias0, c1 = bias0, c2 = bias1, c3 = bias1;
#pragma unroll
            for (int kk = 0; kk < 4; kk++) {
                asm volatile(
                    "mma.sync.aligned.m16n8k8.row.col.f32.tf32.tf32.f32 "
                    "{%0,%1,%2,%3},{%4,%5,%6,%7},{%8,%9},{%0,%1,%2,%3};"
                    : "+f"(c0), "+f"(c1), "+f"(c2), "+f"(c3)
                    : "r"(afr[kk][0]), "r"(afr[kk][1]), "r"(afr[kk][2]), "r"(afr[kk][3]),
                      "r"(bq0[n][kk]), "r"(bq1[n][kk]));
            }
            // C[z, j]: c0 -> (z0,   j=8n+2l4), c1 -> j+1, c2/c3 -> z0+8
            float* p = sbase + (8 * n) * PAD;
            p[0]       = c0;
            p[PAD]     = c1;
            p[8]       = c2;
            p[PAD + 8] = c3;
        }
        __syncthreads();   // all warps' STS for this i complete

        // drain: 64 rows x 512B, full-128B-line STG.128 (8 lanes per row)
        float* dout = out + ((size_t)(i * L_SEQ + jbase)) * CZ;
#pragma unroll
        for (int p = 0; p < 8; p++) {
            const int j  = dj + 32 * (p & 1);
            const int zf = dz + 32 * (p >> 1);
            const float4 v = *(const float4*)(stg + j * PAD + zf);
            *(float4*)(dout + (size_t)j * CZ + zf) = v;
        }
        // no second sync needed: next i uses the other stage buffer, and
        // each warp's own drain precedes its next STS in program order.
    }
}

// ---------------------------------------------------------------------------
extern "C" void kernel_launch(void* const* d_in, const int* in_sizes, int n_in,
                              void* d_out, int out_size)
{
    const float* x   = (const float*)d_in[0];
    const float* lnw = (const float*)d_in[1];
    const float* lnb = (const float*)d_in[2];
    const float* pw  = (const float*)d_in[3];
    const float* pb  = (const float*)d_in[4];
    const float* ow  = (const float*)d_in[5];
    const float* ob  = (const float*)d_in[6];
    float* out = (float*)d_out;

    const int smem2 = 2 * JT * PAD * sizeof(float);   // 67584 B
    cudaFuncSetAttribute(phase2_kernel,
                         cudaFuncAttributeMaxDynamicSharedMemorySize, smem2);

    phase1_kernel<<<dim3(L_SEQ / R1, 2), 256>>>(x, lnw, lnb, pw, pb, ow);
    phase2_kernel<<<dim3(L_SEQ / JT, L_SEQ / I_PER_CTA), 256, smem2>>>(ow, ob, out);
}

// round 8
// speedup vs baseline: 1.3936x; 1.3936x over previous
#include <cuda_runtime.h>
#include <cstdint>

#define L_SEQ 1024
#define C_S   1024
#define DD    32      // inner dim
#define CZ    128     // pairwise dim
#define I_PER_CTA 8
#define JT    64      // j columns per phase2 CTA
#define R1    4       // rows per CTA in phase1

// Scratch (allocation-free rule: __device__ globals)
__device__ float g_q[L_SEQ * DD];
__device__ float g_k[L_SEQ * DD];
__device__ float g_Ak[L_SEQ * CZ];

__device__ __forceinline__ unsigned f2tf(float f) {
    unsigned r;
    asm("cvt.rna.tf32.f32 %0, %1;" : "=r"(r) : "f"(f));
    return r;
}

// ---------------------------------------------------------------------------
// Phase 1: LayerNorm + projection -> q,k [L,32]; Ak[i,z] = sum_d k[i,d]*W2[z,d]
// Grid (L/R1, 2): blockIdx.y selects the d-half (0 -> q, 1 -> k + Ak).
// Ak reads W2 through a bank-padded smem table (fixes the 32-line LDG storm).
// ---------------------------------------------------------------------------
__global__ __launch_bounds__(256) void phase1_kernel(
    const float* __restrict__ x,
    const float* __restrict__ lnw, const float* __restrict__ lnb,
    const float* __restrict__ pw,  const float* __restrict__ pb,
    const float* __restrict__ ow)
{
    __shared__ float4 s4[R1][C_S / 4];       // 16KB normalized rows
    __shared__ float red[2][R1][8];
    __shared__ float qk[R1][DD];             // this half's 32 outputs per row
    __shared__ float ow2s[CZ * (DD + 1)];    // padded W2 table (16.9KB)

    const int tid  = threadIdx.x;
    const int lane = tid & 31;
    const int wid  = tid >> 5;
    const int row0 = blockIdx.x * R1;
    const int h    = blockIdx.y;             // 0: q half, 1: k half

    // preload W2 table (k-half CTAs only); covered by the sync below
    if (h == 1) {
        for (int it = tid; it < CZ * DD; it += 256) {
            const int z = it >> 5, d = it & 31;
            ow2s[z * (DD + 1) + d] = ow[z * (2 * DD) + DD + d];
        }
    }

    // ---- LayerNorm for 4 rows ----
    {
        float4 xv[R1];
        float sum[R1], sq[R1];
#pragma unroll
        for (int r = 0; r < R1; r++) {
            xv[r]  = ((const float4*)(x + (size_t)(row0 + r) * C_S))[tid];
            sum[r] = xv[r].x + xv[r].y + xv[r].z + xv[r].w;
            sq[r]  = fmaf(xv[r].x, xv[r].x, fmaf(xv[r].y, xv[r].y,
                     fmaf(xv[r].z, xv[r].z, xv[r].w * xv[r].w)));
        }
#pragma unroll
        for (int o = 16; o; o >>= 1) {
#pragma unroll
            for (int r = 0; r < R1; r++) {
                sum[r] += __shfl_xor_sync(~0u, sum[r], o);
                sq[r]  += __shfl_xor_sync(~0u, sq[r],  o);
            }
        }
        if (lane == 0) {
#pragma unroll
            for (int r = 0; r < R1; r++) { red[0][r][wid] = sum[r]; red[1][r][wid] = sq[r]; }
        }
        __syncthreads();

        const float4 wv = ((const float4*)lnw)[tid];
        const float4 bv = ((const float4*)lnb)[tid];
#pragma unroll
        for (int r = 0; r < R1; r++) {
            float s = 0.f, q = 0.f;
#pragma unroll
            for (int w = 0; w < 8; w++) { s += red[0][r][w]; q += red[1][r][w]; }
            const float mu   = s * (1.0f / C_S);
            const float var  = q * (1.0f / C_S) - mu * mu;
            const float rstd = rsqrtf(var + 1e-5f);
            float4 sv;
            sv.x = (xv[r].x - mu) * rstd * wv.x + bv.x;
            sv.y = (xv[r].y - mu) * rstd * wv.y + bv.y;
            sv.z = (xv[r].z - mu) * rstd * wv.z + bv.z;
            sv.w = (xv[r].w - mu) * rstd * wv.w + bv.w;
            s4[r][tid] = sv;
        }
    }
    __syncthreads();

    // ---- projection: warp w computes local d = w*4 .. w*4+3 for 4 rows ----
#pragma unroll
    for (int rr = 0; rr < 4; rr++) {
        const int dl = wid * 4 + rr;
        const int dg = h * DD + dl;
        const float4* wr = (const float4*)(pw + (size_t)dg * C_S);
        float acc[R1];
#pragma unroll
        for (int r = 0; r < R1; r++) acc[r] = 0.f;
        for (int c = lane; c < C_S / 4; c += 32) {
            const float4 w4 = wr[c];
#pragma unroll
            for (int r = 0; r < R1; r++) {
                const float4 v = s4[r][c];
                acc[r] = fmaf(v.x, w4.x, fmaf(v.y, w4.y,
                         fmaf(v.z, w4.z, fmaf(v.w, w4.w, acc[r]))));
            }
        }
#pragma unroll
        for (int o = 16; o; o >>= 1) {
#pragma unroll
            for (int r = 0; r < R1; r++) acc[r] += __shfl_xor_sync(~0u, acc[r], o);
        }
        if (lane == 0) {
            const float pbd = pb[dg];
#pragma unroll
            for (int r = 0; r < R1; r++) qk[r][dl] = acc[r] + pbd;
        }
    }
    __syncthreads();

    // ---- write q or k ----
    if (tid < R1 * DD) {
        const int r = tid >> 5, v = tid & 31;
        if (h == 0) g_q[(row0 + r) * DD + v] = qk[r][v];
        else        g_k[(row0 + r) * DD + v] = qk[r][v];
    }

    // ---- Ak (k half only): Ak[i,z] = sum_d k[i,d] * W2[z,d] via smem table ----
    if (h == 1) {
#pragma unroll
        for (int hh = 0; hh < 2; hh++) {
            const int idx = tid + 256 * hh;
            const int r = idx >> 7, z = idx & 127;
            float acc = 0.f;
#pragma unroll
            for (int d = 0; d < DD; d++)
                acc = fmaf(qk[r][d], ow2s[z * (DD + 1) + d], acc);
            g_Ak[(row0 + r) * CZ + z] = acc;
        }
    }
}

// ---------------------------------------------------------------------------
// Phase 2 (transposed operands, no barriers, no staging):
//   out[i,j,z]: M-dim = z, N-dim = j.
//   A[z,d] = Ghat_i[d,z] = k[i,d]*W1[z,d] + W2[z,d]   (regs, rebuilt per i)
//   B[d,j] = q[j,d]                                     (regs, CTA-constant)
//   C seeded with bias[z] = ob[z] - Ak[i,z]
// k rows + Ak rows for all 8 i staged in smem ONCE; per-i loop heads are LDS.
// Accumulators stored directly with streaming STG.32 (quad = 32B contiguous z).
// ---------------------------------------------------------------------------
__global__ __launch_bounds__(256, 2) void phase2_kernel(
    const float* __restrict__ ow, const float* __restrict__ ob,
    float* __restrict__ out)
{
    __shared__ float ks[I_PER_CTA * DD];     // 1KB:  k rows for the CTA's 8 i
    __shared__ float aks[I_PER_CTA * CZ];    // 4KB:  Ak rows for the 8 i

    const int tid  = threadIdx.x;
    const int lane = tid & 31;
    const int wid  = tid >> 5;
    const int l4   = lane & 3;
    const int lg   = lane >> 2;
    const int jbase = blockIdx.x * JT;
    const int ibase = blockIdx.y * I_PER_CTA;

    // one-time staging (coalesced)
    ks[tid] = g_k[ibase * DD + tid];
#pragma unroll
    for (int hh = 0; hh < 4; hh++)
        aks[tid + 256 * hh] = g_Ak[ibase * CZ + tid + 256 * hh];

    const int z0 = wid * 16 + lg;            // accumulator row (z), +8 for upper

    // ---- W1/W2 A-side fragment values, register resident (one-time LDG) ----
    float w1[4][4], w2[4][4];
#pragma unroll
    for (int kk = 0; kk < 4; kk++) {
        const int d0 = l4 + 8 * kk;
        w1[kk][0] = ow[z0 * (2 * DD) + d0];
        w1[kk][1] = ow[(z0 + 8) * (2 * DD) + d0];
        w1[kk][2] = ow[z0 * (2 * DD) + d0 + 4];
        w1[kk][3] = ow[(z0 + 8) * (2 * DD) + d0 + 4];
        w2[kk][0] = ow[z0 * (2 * DD) + DD + d0];
        w2[kk][1] = ow[(z0 + 8) * (2 * DD) + DD + d0];
        w2[kk][2] = ow[z0 * (2 * DD) + DD + d0 + 4];
        w2[kk][3] = ow[(z0 + 8) * (2 * DD) + DD + d0 + 4];
    }

    // ---- q B-side fragments: constant for whole CTA (one-time LDG) ----
    unsigned bq0[8][4], bq1[8][4];
#pragma unroll
    for (int n = 0; n < 8; n++) {
        const int j = jbase + 8 * n + lg;
#pragma unroll
        for (int kk = 0; kk < 4; kk++) {
            const int d0 = l4 + 8 * kk;
            bq0[n][kk] = f2tf(g_q[j * DD + d0]);
            bq1[n][kk] = f2tf(g_q[j * DD + d0 + 4]);
        }
    }

    const float ob0 = ob[z0];
    const float ob1 = ob[z0 + 8];

    __syncthreads();   // ks/aks staged; the ONLY barrier in this kernel

#pragma unroll 1
    for (int ii = 0; ii < I_PER_CTA; ii++) {
        const float bias0 = ob0 - aks[ii * CZ + z0];
        const float bias1 = ob1 - aks[ii * CZ + z0 + 8];

        // build A fragments for this i from smem k row (broadcast LDS)
        unsigned afr[4][4];
#pragma unroll
        for (int kk = 0; kk < 4; kk++) {
            const int d0 = l4 + 8 * kk;
            const float k0 = ks[ii * DD + d0];
            const float k1 = ks[ii * DD + d0 + 4];
            afr[kk][0] = f2tf(fmaf(k0, w1[kk][0], w2[kk][0]));
            afr[kk][1] = f2tf(fmaf(k0, w1[kk][1], w2[kk][1]));
            afr[kk][2] = f2tf(fmaf(k1, w1[kk][2], w2[kk][2]));
            afr[kk][3] = f2tf(fmaf(k1, w1[kk][3], w2[kk][3]));
        }

        // direct streaming stores: c0->(j,z0) c1->(j+1,z0) c2->(j,z0+8) c3->(j+1,z0+8)
        float* obase = out + ((size_t)((ibase + ii) * L_SEQ) + jbase + 2 * l4) * CZ + z0;

#pragma unroll
        for (int n = 0; n < 8; n++) {
            float c0 = bias0, c1 = bias0, c2 = bias1, c3 = bias1;
#pragma unroll
            for (int kk = 0; kk < 4; kk++) {
                asm volatile(
                    "mma.sync.aligned.m16n8k8.row.col.f32.tf32.tf32.f32 "
                    "{%0,%1,%2,%3},{%4,%5,%6,%7},{%8,%9},{%0,%1,%2,%3};"
                    : "+f"(c0), "+f"(c1), "+f"(c2), "+f"(c3)
                    : "r"(afr[kk][0]), "r"(afr[kk][1]), "r"(afr[kk][2]), "r"(afr[kk][3]),
                      "r"(bq0[n][kk]), "r"(bq1[n][kk]));
            }
            float* p = obase + (size_t)(8 * n) * CZ;
            __stcs(p,          c0);
            __stcs(p + CZ,     c1);
            __stcs(p + 8,      c2);
            __stcs(p + CZ + 8, c3);
        }
    }
}

// ---------------------------------------------------------------------------
extern "C" void kernel_launch(void* const* d_in, const int* in_sizes, int n_in,
                              void* d_out, int out_size)
{
    const float* x   = (const float*)d_in[0];
    const float* lnw = (const float*)d_in[1];
    const float* lnb = (const float*)d_in[2];
    const float* pw  = (const float*)d_in[3];
    const float* pb  = (const float*)d_in[4];
    const float* ow  = (const float*)d_in[5];
    const float* ob  = (const float*)d_in[6];
    float* out = (float*)d_out;

    phase1_kernel<<<dim3(L_SEQ / R1, 2), 256>>>(x, lnw, lnb, pw, pb, ow);
    phase2_kernel<<<dim3(L_SEQ / JT, L_SEQ / I_PER_CTA), 256>>>(ow, ob, out);
}

// round 9
// speedup vs baseline: 1.4027x; 1.0065x over previous
#include <cuda_runtime.h>
#include <cuda.h>
#include <cstdint>

#define L_SEQ 1024
#define C_S   1024
#define DD    32      // inner dim
#define CZ    128     // pairwise dim
#define I_PER_CTA 8
#define JT    64      // j columns per phase2 CTA
#define R1    4       // rows per CTA in phase1

// Scratch (allocation-free rule: __device__ globals)
__device__ float g_q[L_SEQ * DD];
__device__ float g_k[L_SEQ * DD];
__device__ float g_Ak[L_SEQ * CZ];

__device__ __forceinline__ unsigned f2tf(float f) {
    unsigned r;
    asm("cvt.rna.tf32.f32 %0, %1;" : "=r"(r) : "f"(f));
    return r;
}

// ---------------------------------------------------------------------------
// Phase 1: LayerNorm + projection -> q,k [L,32]; Ak[i,z] = sum_d k[i,d]*W2[z,d]
// Grid (L/R1, 2): blockIdx.y selects the d-half (0 -> q, 1 -> k + Ak).
// ---------------------------------------------------------------------------
__global__ __launch_bounds__(256) void phase1_kernel(
    const float* __restrict__ x,
    const float* __restrict__ lnw, const float* __restrict__ lnb,
    const float* __restrict__ pw,  const float* __restrict__ pb,
    const float* __restrict__ ow)
{
    __shared__ float4 s4[R1][C_S / 4];       // 16KB normalized rows
    __shared__ float red[2][R1][8];
    __shared__ float qk[R1][DD];
    __shared__ float ow2s[CZ * (DD + 1)];    // padded W2 table

    const int tid  = threadIdx.x;
    const int lane = tid & 31;
    const int wid  = tid >> 5;
    const int row0 = blockIdx.x * R1;
    const int h    = blockIdx.y;             // 0: q half, 1: k half

    if (h == 1) {
        for (int it = tid; it < CZ * DD; it += 256) {
            const int z = it >> 5, d = it & 31;
            ow2s[z * (DD + 1) + d] = ow[z * (2 * DD) + DD + d];
        }
    }

    // ---- LayerNorm for 4 rows ----
    {
        float4 xv[R1];
        float sum[R1], sq[R1];
#pragma unroll
        for (int r = 0; r < R1; r++) {
            xv[r]  = ((const float4*)(x + (size_t)(row0 + r) * C_S))[tid];
            sum[r] = xv[r].x + xv[r].y + xv[r].z + xv[r].w;
            sq[r]  = fmaf(xv[r].x, xv[r].x, fmaf(xv[r].y, xv[r].y,
                     fmaf(xv[r].z, xv[r].z, xv[r].w * xv[r].w)));
        }
#pragma unroll
        for (int o = 16; o; o >>= 1) {
#pragma unroll
            for (int r = 0; r < R1; r++) {
                sum[r] += __shfl_xor_sync(~0u, sum[r], o);
                sq[r]  += __shfl_xor_sync(~0u, sq[r],  o);
            }
        }
        if (lane == 0) {
#pragma unroll
            for (int r = 0; r < R1; r++) { red[0][r][wid] = sum[r]; red[1][r][wid] = sq[r]; }
        }
        __syncthreads();

        const float4 wv = ((const float4*)lnw)[tid];
        const float4 bv = ((const float4*)lnb)[tid];
#pragma unroll
        for (int r = 0; r < R1; r++) {
            float s = 0.f, q = 0.f;
#pragma unroll
            for (int w = 0; w < 8; w++) { s += red[0][r][w]; q += red[1][r][w]; }
            const float mu   = s * (1.0f / C_S);
            const float var  = q * (1.0f / C_S) - mu * mu;
            const float rstd = rsqrtf(var + 1e-5f);
            float4 sv;
            sv.x = (xv[r].x - mu) * rstd * wv.x + bv.x;
            sv.y = (xv[r].y - mu) * rstd * wv.y + bv.y;
            sv.z = (xv[r].z - mu) * rstd * wv.z + bv.z;
            sv.w = (xv[r].w - mu) * rstd * wv.w + bv.w;
            s4[r][tid] = sv;
        }
    }
    __syncthreads();

    // ---- projection: warp w computes local d = w*4 .. w*4+3 for 4 rows ----
#pragma unroll
    for (int rr = 0; rr < 4; rr++) {
        const int dl = wid * 4 + rr;
        const int dg = h * DD + dl;
        const float4* wr = (const float4*)(pw + (size_t)dg * C_S);
        float acc[R1];
#pragma unroll
        for (int r = 0; r < R1; r++) acc[r] = 0.f;
        for (int c = lane; c < C_S / 4; c += 32) {
            const float4 w4 = wr[c];
#pragma unroll
            for (int r = 0; r < R1; r++) {
                const float4 v = s4[r][c];
                acc[r] = fmaf(v.x, w4.x, fmaf(v.y, w4.y,
                         fmaf(v.z, w4.z, fmaf(v.w, w4.w, acc[r]))));
            }
        }
#pragma unroll
        for (int o = 16; o; o >>= 1) {
#pragma unroll
            for (int r = 0; r < R1; r++) acc[r] += __shfl_xor_sync(~0u, acc[r], o);
        }
        if (lane == 0) {
            const float pbd = pb[dg];
#pragma unroll
            for (int r = 0; r < R1; r++) qk[r][dl] = acc[r] + pbd;
        }
    }
    __syncthreads();

    if (tid < R1 * DD) {
        const int r = tid >> 5, v = tid & 31;
        if (h == 0) g_q[(row0 + r) * DD + v] = qk[r][v];
        else        g_k[(row0 + r) * DD + v] = qk[r][v];
    }

    if (h == 1) {
#pragma unroll
        for (int hh = 0; hh < 2; hh++) {
            const int idx = tid + 256 * hh;
            const int r = idx >> 7, z = idx & 127;
            float acc = 0.f;
#pragma unroll
            for (int d = 0; d < DD; d++)
                acc = fmaf(qk[r][d], ow2s[z * (DD + 1) + d], acc);
            g_Ak[(row0 + r) * CZ + z] = acc;
        }
    }
}

// ---------------------------------------------------------------------------
// Phase 2: transposed mma (M=z, N=j) + SW128-swizzled SMEM staging + TMA store.
// Dynamic smem layout:
//   [0,      32768)  stage buf 0 (4 chunks x 64 rows x 128B, SW128)
//   [32768,  65536)  stage buf 1
//   [65536,  66560)  ks  (8 k rows)
//   [66560,  70656)  aks (8 Ak rows)
// ---------------------------------------------------------------------------
#define SMEM2_BYTES (32768 * 2 + 1024 + 4096)

extern __shared__ char smem_dyn[];

__device__ __forceinline__ uint32_t swz(uint32_t b) {
    return b ^ ((b >> 3) & 0x70);
}

__global__ __launch_bounds__(256, 2) void phase2_kernel(
    const __grid_constant__ CUtensorMap tmap,
    const float* __restrict__ ow, const float* __restrict__ ob)
{
    float* ks  = (float*)(smem_dyn + 65536);
    float* aks = (float*)(smem_dyn + 66560);

    uint32_t smem_u32;
    asm("{ .reg .u64 t; cvta.to.shared.u64 t, %1; cvt.u32.u64 %0, t; }"
        : "=r"(smem_u32) : "l"(smem_dyn));

    const int tid  = threadIdx.x;
    const int lane = tid & 31;
    const int wid  = tid >> 5;
    const int l4   = lane & 3;
    const int lg   = lane >> 2;
    const int jbase = blockIdx.x * JT;
    const int ibase = blockIdx.y * I_PER_CTA;

    // one-time staging of k / Ak rows for this CTA's 8 i
    ks[tid] = g_k[ibase * DD + tid];
#pragma unroll
    for (int hh = 0; hh < 4; hh++)
        aks[tid + 256 * hh] = g_Ak[ibase * CZ + tid + 256 * hh];

    const int z0 = wid * 16 + lg;            // global z row; +8 for upper

    // ---- W1/W2 fragment values, register resident ----
    float w1[4][4], w2[4][4];
#pragma unroll
    for (int kk = 0; kk < 4; kk++) {
        const int d0 = l4 + 8 * kk;
        w1[kk][0] = ow[z0 * (2 * DD) + d0];
        w1[kk][1] = ow[(z0 + 8) * (2 * DD) + d0];
        w1[kk][2] = ow[z0 * (2 * DD) + d0 + 4];
        w1[kk][3] = ow[(z0 + 8) * (2 * DD) + d0 + 4];
        w2[kk][0] = ow[z0 * (2 * DD) + DD + d0];
        w2[kk][1] = ow[(z0 + 8) * (2 * DD) + DD + d0];
        w2[kk][2] = ow[z0 * (2 * DD) + DD + d0 + 4];
        w2[kk][3] = ow[(z0 + 8) * (2 * DD) + DD + d0 + 4];
    }

    // ---- q B-side fragments: constant for whole CTA ----
    unsigned bq0[8][4], bq1[8][4];
#pragma unroll
    for (int n = 0; n < 8; n++) {
        const int j = jbase + 8 * n + lg;
#pragma unroll
        for (int kk = 0; kk < 4; kk++) {
            const int d0 = l4 + 8 * kk;
            bq0[n][kk] = f2tf(g_q[j * DD + d0]);
            bq1[n][kk] = f2tf(g_q[j * DD + d0 + 4]);
        }
    }

    const float ob0 = ob[z0];
    const float ob1 = ob[z0 + 8];

    // swizzled staging offsets (verified conflict-free for all four stores)
    const int ch   = wid >> 1;                      // 32-z swizzle chunk
    const int zin  = 16 * (wid & 1) + lg;           // z within chunk
    const uint32_t b0 = (uint32_t)(ch * 8192 + (2 * l4) * 128 + zin * 4);
    const uint32_t p0 = swz(b0);
    const uint32_t p1 = swz(b0 + 128);              // j+1
    const uint32_t p2 = swz(b0 + 32);               // z0+8
    const uint32_t p3 = swz(b0 + 128 + 32);         // j+1, z0+8

    __syncthreads();   // ks/aks staged

#pragma unroll 1
    for (int ii = 0; ii < I_PER_CTA; ii++) {
        char* stg = smem_dyn + (ii & 1) * 32768;

        const float bias0 = ob0 - aks[ii * CZ + z0];
        const float bias1 = ob1 - aks[ii * CZ + z0 + 8];

        // build A fragments for this i from smem k row (broadcast LDS)
        unsigned afr[4][4];
#pragma unroll
        for (int kk = 0; kk < 4; kk++) {
            const int d0 = l4 + 8 * kk;
            const float k0 = ks[ii * DD + d0];
            const float k1 = ks[ii * DD + d0 + 4];
            afr[kk][0] = f2tf(fmaf(k0, w1[kk][0], w2[kk][0]));
            afr[kk][1] = f2tf(fmaf(k0, w1[kk][1], w2[kk][1]));
            afr[kk][2] = f2tf(fmaf(k1, w1[kk][2], w2[kk][2]));
            afr[kk][3] = f2tf(fmaf(k1, w1[kk][3], w2[kk][3]));
        }

#pragma unroll
        for (int n = 0; n < 8; n++) {
            float c0 = bias0, c1 = bias0, c2 = bias1, c3 = bias1;
#pragma unroll
            for (int kk = 0; kk < 4; kk++) {
                asm volatile(
                    "mma.sync.aligned.m16n8k8.row.col.f32.tf32.tf32.f32 "
                    "{%0,%1,%2,%3},{%4,%5,%6,%7},{%8,%9},{%0,%1,%2,%3};"
                    : "+f"(c0), "+f"(c1), "+f"(c2), "+f"(c3)
                    : "r"(afr[kk][0]), "r"(afr[kk][1]), "r"(afr[kk][2]), "r"(afr[kk][3]),
                      "r"(bq0[n][kk]), "r"(bq1[n][kk]));
            }
            const uint32_t nb = (uint32_t)(n << 10);
            *(float*)(stg + p0 + nb) = c0;
            *(float*)(stg + p1 + nb) = c1;
            *(float*)(stg + p2 + nb) = c2;
            *(float*)(stg + p3 + nb) = c3;
        }

        asm volatile("fence.proxy.async.shared::cta;" ::: "memory");
        __syncthreads();   // all STS for this i visible

        if (tid == 0) {
            const uint32_t sbase = smem_u32 + (ii & 1) * 32768;
            const int row = (ibase + ii) * L_SEQ + jbase;
#pragma unroll
            for (int c = 0; c < 4; c++) {
                asm volatile(
                    "cp.async.bulk.tensor.3d.global.shared::cta.tile.bulk_group "
                    "[%0, {%1, %2, %3}], [%4];"
                    :: "l"(&tmap), "r"(0), "r"(c), "r"(row),
                       "r"(sbase + c * 8192) : "memory");
            }
            asm volatile("cp.async.bulk.commit_group;" ::: "memory");
            // allow 1 group in flight; guarantees buf (ii&1) free at ii+2
            asm volatile("cp.async.bulk.wait_group.read 1;" ::: "memory");
        }
        __syncthreads();
    }

    // drain all pending TMA stores before exit
    if (tid == 0)
        asm volatile("cp.async.bulk.wait_group 0;" ::: "memory");
}

// ---------------------------------------------------------------------------
typedef CUresult (*EncodeFn)(
    CUtensorMap*, CUtensorMapDataType, cuuint32_t, void*,
    const cuuint64_t*, const cuuint64_t*, const cuuint32_t*, const cuuint32_t*,
    CUtensorMapInterleave, CUtensorMapSwizzle, CUtensorMapL2promotion,
    CUtensorMapFloatOOBfill);

extern "C" void kernel_launch(void* const* d_in, const int* in_sizes, int n_in,
                              void* d_out, int out_size)
{
    const float* x   = (const float*)d_in[0];
    const float* lnw = (const float*)d_in[1];
    const float* lnb = (const float*)d_in[2];
    const float* pw  = (const float*)d_in[3];
    const float* pb  = (const float*)d_in[4];
    const float* ow  = (const float*)d_in[5];
    const float* ob  = (const float*)d_in[6];

    // Build TMA descriptor for the output viewed as [row=1M][chunk=4][32 f32]
    CUtensorMap tmap;
    {
        void* fn = nullptr;
        cudaDriverEntryPointQueryResult qr;
        cudaGetDriverEntryPoint("cuTensorMapEncodeTiled", &fn,
                                cudaEnableDefault, &qr);
        EncodeFn enc = (EncodeFn)fn;
        cuuint64_t dims[3]    = {32, 4, (cuuint64_t)L_SEQ * L_SEQ};
        cuuint64_t strides[2] = {128, 512};          // bytes
        cuuint32_t box[3]     = {32, 1, 64};
        cuuint32_t es[3]      = {1, 1, 1};
        enc(&tmap, CU_TENSOR_MAP_DATA_TYPE_FLOAT32, 3, d_out,
            dims, strides, box, es,
            CU_TENSOR_MAP_INTERLEAVE_NONE, CU_TENSOR_MAP_SWIZZLE_128B,
            CU_TENSOR_MAP_L2_PROMOTION_NONE, CU_TENSOR_MAP_FLOAT_OOB_FILL_NONE);
    }

    cudaFuncSetAttribute(phase2_kernel,
                         cudaFuncAttributeMaxDynamicSharedMemorySize, SMEM2_BYTES);

    phase1_kernel<<<dim3(L_SEQ / R1, 2), 256>>>(x, lnw, lnb, pw, pb, ow);
    phase2_kernel<<<dim3(L_SEQ / JT, L_SEQ / I_PER_CTA), 256, SMEM2_BYTES>>>(
        tmap, ow, ob);
}

// round 10
// speedup vs baseline: 1.5477x; 1.1034x over previous
#include <cuda_runtime.h>
#include <cuda.h>
#include <cstdint>

#define L_SEQ 1024
#define C_S   1024
#define DD    32      // inner dim
#define CZ    128     // pairwise dim
#define I_PER_CTA 16
#define JT    64      // j columns per phase2 CTA
#define R1    8       // rows per CTA in phase1

#define BUFB  32768   // one staging buffer (64 rows x 512B)
#define NBUF  3
// dynamic smem: 3 bufs | ks (16*32*4=2048) | aks (16*128*4=8192)
#define KS_OFF   (NBUF * BUFB)
#define AKS_OFF  (KS_OFF + I_PER_CTA * DD * 4)
#define SMEM2_BYTES (AKS_OFF + I_PER_CTA * CZ * 4)   // 108544

// Scratch (allocation-free rule: __device__ globals)
__device__ float g_q[L_SEQ * DD];
__device__ float g_k[L_SEQ * DD];
__device__ float g_Ak[L_SEQ * CZ];

__device__ __forceinline__ unsigned f2tf(float f) {
    unsigned r;
    asm("cvt.rna.tf32.f32 %0, %1;" : "=r"(r) : "f"(f));
    return r;
}

__device__ __forceinline__ uint32_t swz(uint32_t b) {
    return b ^ ((b >> 3) & 0x70);
}

// ---------------------------------------------------------------------------
// Phase 1: LayerNorm + projection -> q,k [L,32]; Ak[i,z] = sum_d k[i,d]*W2[z,d]
// Grid (L/R1, 2): blockIdx.y selects the d-half (0 -> q, 1 -> k + Ak).
// R1=8 rows per CTA halves proj_w L2 traffic vs R1=4.
// ---------------------------------------------------------------------------
__global__ __launch_bounds__(256) void phase1_kernel(
    const float* __restrict__ x,
    const float* __restrict__ lnw, const float* __restrict__ lnb,
    const float* __restrict__ pw,  const float* __restrict__ pb,
    const float* __restrict__ ow)
{
    __shared__ float4 s4[R1][C_S / 4];       // 32KB normalized rows (reused for W2)
    __shared__ float red[2][R1][8];
    __shared__ float qk[R1][DD];

    const int tid  = threadIdx.x;
    const int lane = tid & 31;
    const int wid  = tid >> 5;
    const int row0 = blockIdx.x * R1;
    const int h    = blockIdx.y;             // 0: q half, 1: k half

    // ---- LayerNorm for 8 rows ----
    {
        float4 xv[R1];
        float sum[R1], sq[R1];
#pragma unroll
        for (int r = 0; r < R1; r++) {
            xv[r]  = ((const float4*)(x + (size_t)(row0 + r) * C_S))[tid];
            sum[r] = xv[r].x + xv[r].y + xv[r].z + xv[r].w;
            sq[r]  = fmaf(xv[r].x, xv[r].x, fmaf(xv[r].y, xv[r].y,
                     fmaf(xv[r].z, xv[r].z, xv[r].w * xv[r].w)));
        }
#pragma unroll
        for (int o = 16; o; o >>= 1) {
#pragma unroll
            for (int r = 0; r < R1; r++) {
                sum[r] += __shfl_xor_sync(~0u, sum[r], o);
                sq[r]  += __shfl_xor_sync(~0u, sq[r],  o);
            }
        }
        if (lane == 0) {
#pragma unroll
            for (int r = 0; r < R1; r++) { red[0][r][wid] = sum[r]; red[1][r][wid] = sq[r]; }
        }
        __syncthreads();

        const float4 wv = ((const float4*)lnw)[tid];
        const float4 bv = ((const float4*)lnb)[tid];
#pragma unroll
        for (int r = 0; r < R1; r++) {
            float s = 0.f, q = 0.f;
#pragma unroll
            for (int w = 0; w < 8; w++) { s += red[0][r][w]; q += red[1][r][w]; }
            const float mu   = s * (1.0f / C_S);
            const float var  = q * (1.0f / C_S) - mu * mu;
            const float rstd = rsqrtf(var + 1e-5f);
            float4 sv;
            sv.x = (xv[r].x - mu) * rstd * wv.x + bv.x;
            sv.y = (xv[r].y - mu) * rstd * wv.y + bv.y;
            sv.z = (xv[r].z - mu) * rstd * wv.z + bv.z;
            sv.w = (xv[r].w - mu) * rstd * wv.w + bv.w;
            s4[r][tid] = sv;
        }
    }
    __syncthreads();

    // ---- projection: warp w computes local d = w*4 .. w*4+3 for 8 rows ----
#pragma unroll
    for (int rr = 0; rr < 4; rr++) {
        const int dl = wid * 4 + rr;
        const int dg = h * DD + dl;
        const float4* wr = (const float4*)(pw + (size_t)dg * C_S);
        float acc[R1];
#pragma unroll
        for (int r = 0; r < R1; r++) acc[r] = 0.f;
        for (int c = lane; c < C_S / 4; c += 32) {
            const float4 w4 = wr[c];
#pragma unroll
            for (int r = 0; r < R1; r++) {
                const float4 v = s4[r][c];
                acc[r] = fmaf(v.x, w4.x, fmaf(v.y, w4.y,
                         fmaf(v.z, w4.z, fmaf(v.w, w4.w, acc[r]))));
            }
        }
#pragma unroll
        for (int o = 16; o; o >>= 1) {
#pragma unroll
            for (int r = 0; r < R1; r++) acc[r] += __shfl_xor_sync(~0u, acc[r], o);
        }
        if (lane == 0) {
            const float pbd = pb[dg];
#pragma unroll
            for (int r = 0; r < R1; r++) qk[r][dl] = acc[r] + pbd;
        }
    }
    __syncthreads();   // qk complete; also: all reads of s4 done

    // ---- write q or k (8 rows x 32 = 256 values = one per thread) ----
    {
        const int r = tid >> 5, v = tid & 31;
        if (h == 0) g_q[(row0 + r) * DD + v] = qk[r][v];
        else        g_k[(row0 + r) * DD + v] = qk[r][v];
    }

    // ---- Ak (k half only) via padded W2 table in reused s4 space ----
    if (h == 1) {
        float* ow2s = (float*)s4;            // CZ*(DD+1) = 4224 floats < 8192
        for (int it = tid; it < CZ * DD; it += 256) {
            const int z = it >> 5, d = it & 31;
            ow2s[z * (DD + 1) + d] = ow[z * (2 * DD) + DD + d];
        }
        __syncthreads();
#pragma unroll
        for (int hh = 0; hh < 4; hh++) {
            const int idx = tid + 256 * hh;
            const int r = idx >> 7, z = idx & 127;
            float acc = 0.f;
#pragma unroll
            for (int d = 0; d < DD; d++)
                acc = fmaf(qk[r][d], ow2s[z * (DD + 1) + d], acc);
            g_Ak[(row0 + r) * CZ + z] = acc;
        }
    }
}

// ---------------------------------------------------------------------------
// Phase 2: transposed mma (M=z, N=j), SW128 staging, ONE TMA store per i,
// 3-deep TMA pipeline (wait_group.read 2), q fragments via coalesced smem.
// ---------------------------------------------------------------------------
extern __shared__ char smem_dyn[];

__global__ __launch_bounds__(256, 2) void phase2_kernel(
    const __grid_constant__ CUtensorMap tmap,
    const float* __restrict__ ow, const float* __restrict__ ob)
{
    float* ks  = (float*)(smem_dyn + KS_OFF);
    float* aks = (float*)(smem_dyn + AKS_OFF);

    uint32_t smem_u32;
    asm("{ .reg .u64 t; cvta.to.shared.u64 t, %1; cvt.u32.u64 %0, t; }"
        : "=r"(smem_u32) : "l"(smem_dyn));

    const int tid  = threadIdx.x;
    const int lane = tid & 31;
    const int wid  = tid >> 5;
    const int l4   = lane & 3;
    const int lg   = lane >> 2;
    const int jbase = blockIdx.x * JT;
    const int ibase = blockIdx.y * I_PER_CTA;

    // ---- one-time staging: q tile (padded rows of 36f, in buf0 space), k, Ak ----
    float* qs = (float*)smem_dyn;            // 64*36*4 = 9216B, temporary
    for (int it = tid; it < JT * DD; it += 256) {
        const int j = it >> 5, d = it & 31;
        qs[j * 36 + d] = g_q[(jbase + j) * DD + d];
    }
    ks[tid]       = g_k[ibase * DD + tid];
    ks[tid + 256] = g_k[ibase * DD + tid + 256];
#pragma unroll
    for (int hh = 0; hh < 8; hh++)
        aks[tid + 256 * hh] = g_Ak[ibase * CZ + tid + 256 * hh];

    const int z0 = wid * 16 + lg;            // global z row; +8 for upper

    // ---- W1/W2 fragment values, register resident (one-time) ----
    float w1[4][4], w2[4][4];
#pragma unroll
    for (int kk = 0; kk < 4; kk++) {
        const int d0 = l4 + 8 * kk;
        w1[kk][0] = ow[z0 * (2 * DD) + d0];
        w1[kk][1] = ow[(z0 + 8) * (2 * DD) + d0];
        w1[kk][2] = ow[z0 * (2 * DD) + d0 + 4];
        w1[kk][3] = ow[(z0 + 8) * (2 * DD) + d0 + 4];
        w2[kk][0] = ow[z0 * (2 * DD) + DD + d0];
        w2[kk][1] = ow[(z0 + 8) * (2 * DD) + DD + d0];
        w2[kk][2] = ow[z0 * (2 * DD) + DD + d0 + 4];
        w2[kk][3] = ow[(z0 + 8) * (2 * DD) + DD + d0 + 4];
    }
    const float ob0 = ob[z0];
    const float ob1 = ob[z0 + 8];

    __syncthreads();   // qs/ks/aks staged

    // ---- q B-side fragments from smem (pad-36 rows -> conflict-free LDS) ----
    unsigned bq0[8][4], bq1[8][4];
#pragma unroll
    for (int n = 0; n < 8; n++) {
        const float* qrow = qs + (8 * n + lg) * 36;
#pragma unroll
        for (int kk = 0; kk < 4; kk++) {
            const int d0 = l4 + 8 * kk;
            bq0[n][kk] = f2tf(qrow[d0]);
            bq1[n][kk] = f2tf(qrow[d0 + 4]);
        }
    }
    __syncthreads();   // qs reads done; buf0 may be overwritten

    // staging offsets: smem layout for box {32,4,64} = swz(j*512 + z*4)
    const uint32_t p0 = swz((uint32_t)(2 * l4) * 512 + (uint32_t)z0 * 4);
    const uint32_t p1 = p0 ^ 0x240;          // j+1
    const uint32_t p2 = p0 ^ 32;             // z0+8
    const uint32_t p3 = p0 ^ 0x260;          // j+1, z0+8

    int buf = 0;
#pragma unroll 1
    for (int ii = 0; ii < I_PER_CTA; ii++) {
        char* stg = smem_dyn + buf * BUFB;

        const float bias0 = ob0 - aks[ii * CZ + z0];
        const float bias1 = ob1 - aks[ii * CZ + z0 + 8];

        // build A fragments for this i from smem k row (broadcast LDS)
        unsigned afr[4][4];
#pragma unroll
        for (int kk = 0; kk < 4; kk++) {
            const int d0 = l4 + 8 * kk;
            const float k0 = ks[ii * DD + d0];
            const float k1 = ks[ii * DD + d0 + 4];
            afr[kk][0] = f2tf(fmaf(k0, w1[kk][0], w2[kk][0]));
            afr[kk][1] = f2tf(fmaf(k0, w1[kk][1], w2[kk][1]));
            afr[kk][2] = f2tf(fmaf(k1, w1[kk][2], w2[kk][2]));
            afr[kk][3] = f2tf(fmaf(k1, w1[kk][3], w2[kk][3]));
        }

#pragma unroll
        for (int n = 0; n < 8; n++) {
            float c0 = bias0, c1 = bias0, c2 = bias1, c3 = bias1;
#pragma unroll
            for (int kk = 0; kk < 4; kk++) {
                asm volatile(
                    "mma.sync.aligned.m16n8k8.row.col.f32.tf32.tf32.f32 "
                    "{%0,%1,%2,%3},{%4,%5,%6,%7},{%8,%9},{%0,%1,%2,%3};"
                    : "+f"(c0), "+f"(c1), "+f"(c2), "+f"(c3)
                    : "r"(afr[kk][0]), "r"(afr[kk][1]), "r"(afr[kk][2]), "r"(afr[kk][3]),
                      "r"(bq0[n][kk]), "r"(bq1[n][kk]));
            }
            const uint32_t nb = (uint32_t)(n << 12);   // j += 8 -> +4096B
            *(float*)(stg + p0 + nb) = c0;
            *(float*)(stg + p1 + nb) = c1;
            *(float*)(stg + p2 + nb) = c2;
            *(float*)(stg + p3 + nb) = c3;
        }

        asm volatile("fence.proxy.async.shared::cta;" ::: "memory");
        __syncthreads();   // all STS for this i visible

        if (tid == 0) {
            const uint32_t sbase = smem_u32 + buf * BUFB;
            const int row = (ibase + ii) * L_SEQ + jbase;
            asm volatile(
                "cp.async.bulk.tensor.3d.global.shared::cta.tile.bulk_group "
                "[%0, {%1, %2, %3}], [%4];"
                :: "l"(&tmap), "r"(0), "r"(0), "r"(row), "r"(sbase) : "memory");
            asm volatile("cp.async.bulk.commit_group;" ::: "memory");
            // <=2 groups pending: buffer written at ii is free again at ii+3
            asm volatile("cp.async.bulk.wait_group.read 2;" ::: "memory");
        }
        __syncthreads();

        buf = (buf == NBUF - 1) ? 0 : buf + 1;
    }

    if (tid == 0)
        asm volatile("cp.async.bulk.wait_group 0;" ::: "memory");
}

// ---------------------------------------------------------------------------
typedef CUresult (*EncodeFn)(
    CUtensorMap*, CUtensorMapDataType, cuuint32_t, void*,
    const cuuint64_t*, const cuuint64_t*, const cuuint32_t*, const cuuint32_t*,
    CUtensorMapInterleave, CUtensorMapSwizzle, CUtensorMapL2promotion,
    CUtensorMapFloatOOBfill);

extern "C" void kernel_launch(void* const* d_in, const int* in_sizes, int n_in,
                              void* d_out, int out_size)
{
    const float* x   = (const float*)d_in[0];
    const float* lnw = (const float*)d_in[1];
    const float* lnb = (const float*)d_in[2];
    const float* pw  = (const float*)d_in[3];
    const float* pb  = (const float*)d_in[4];
    const float* ow  = (const float*)d_in[5];
    const float* ob  = (const float*)d_in[6];

    // Output viewed as [row = i*L+j : 1M][chunk : 4][32 f32]; one 32KB box/tile.
    CUtensorMap tmap;
    {
        void* fn = nullptr;
        cudaDriverEntryPointQueryResult qr;
        cudaGetDriverEntryPoint("cuTensorMapEncodeTiled", &fn,
                                cudaEnableDefault, &qr);
        EncodeFn enc = (EncodeFn)fn;
        cuuint64_t dims[3]    = {32, 4, (cuuint64_t)L_SEQ * L_SEQ};
        cuuint64_t strides[2] = {128, 512};          // bytes
        cuuint32_t box[3]     = {32, 4, JT};
        cuuint32_t es[3]      = {1, 1, 1};
        enc(&tmap, CU_TENSOR_MAP_DATA_TYPE_FLOAT32, 3, d_out,
            dims, strides, box, es,
            CU_TENSOR_MAP_INTERLEAVE_NONE, CU_TENSOR_MAP_SWIZZLE_128B,
            CU_TENSOR_MAP_L2_PROMOTION_NONE, CU_TENSOR_MAP_FLOAT_OOB_FILL_NONE);
    }

    cudaFuncSetAttribute(phase2_kernel,
                         cudaFuncAttributeMaxDynamicSharedMemorySize, SMEM2_BYTES);

    phase1_kernel<<<dim3(L_SEQ / R1, 2), 256>>>(x, lnw, lnb, pw, pb, ow);
    phase2_kernel<<<dim3(L_SEQ / JT, L_SEQ / I_PER_CTA), 256, SMEM2_BYTES>>>(
        tmap, ow, ob);
}

// round 11
// speedup vs baseline: 1.6807x; 1.0859x over previous
#include <cuda_runtime.h>
#include <cuda.h>
#include <cuda_fp16.h>
#include <cstdint>

#define L_SEQ 1024
#define C_S   1024
#define DD    32      // inner dim
#define CZ    128     // pairwise dim
#define I_PER_CTA 16
#define JT    64      // j columns per phase2 CTA
#define R1    8       // rows per CTA in phase1

#define BUFB  32768   // one staging buffer (64 rows x 512B)
#define NBUF  2
#define KSH_OFF  (NBUF * BUFB)                       // f16x2 k pairs: 16 i x 16
#define SMEM2_BYTES (KSH_OFF + I_PER_CTA * 16 * 4)   // 66560

// Scratch (allocation-free rule: __device__ globals)
__device__ float g_q[L_SEQ * DD];
__device__ float g_k[L_SEQ * DD];
__device__ float g_Ak[L_SEQ * CZ];

__device__ __forceinline__ uint32_t swz(uint32_t b) {
    return b ^ ((b >> 3) & 0x70);
}
__device__ __forceinline__ unsigned packh2(float lo, float hi) {
    __half2 h = __floats2half2_rn(lo, hi);
    return *reinterpret_cast<unsigned*>(&h);
}
__device__ __forceinline__ unsigned hfma2u(unsigned a, unsigned b, unsigned c) {
    __half2 r = __hfma2(*reinterpret_cast<__half2*>(&a),
                        *reinterpret_cast<__half2*>(&b),
                        *reinterpret_cast<__half2*>(&c));
    return *reinterpret_cast<unsigned*>(&r);
}

// ---------------------------------------------------------------------------
// Phase 1: LayerNorm + projection -> q,k [L,32]; Ak[i,z] = sum_d k[i,d]*W2[z,d]
// Grid (L/R1, 2): blockIdx.y selects the d-half (0 -> q, 1 -> k + Ak).
// ---------------------------------------------------------------------------
__global__ __launch_bounds__(256) void phase1_kernel(
    const float* __restrict__ x,
    const float* __restrict__ lnw, const float* __restrict__ lnb,
    const float* __restrict__ pw,  const float* __restrict__ pb,
    const float* __restrict__ ow)
{
    __shared__ float4 s4[R1][C_S / 4];       // 32KB normalized rows (reused for W2)
    __shared__ float red[2][R1][8];
    __shared__ float qk[R1][DD];

    const int tid  = threadIdx.x;
    const int lane = tid & 31;
    const int wid  = tid >> 5;
    const int row0 = blockIdx.x * R1;
    const int h    = blockIdx.y;             // 0: q half, 1: k half

    // ---- LayerNorm for 8 rows ----
    {
        float4 xv[R1];
        float sum[R1], sq[R1];
#pragma unroll
        for (int r = 0; r < R1; r++) {
            xv[r]  = ((const float4*)(x + (size_t)(row0 + r) * C_S))[tid];
            sum[r] = xv[r].x + xv[r].y + xv[r].z + xv[r].w;
            sq[r]  = fmaf(xv[r].x, xv[r].x, fmaf(xv[r].y, xv[r].y,
                     fmaf(xv[r].z, xv[r].z, xv[r].w * xv[r].w)));
        }
#pragma unroll
        for (int o = 16; o; o >>= 1) {
#pragma unroll
            for (int r = 0; r < R1; r++) {
                sum[r] += __shfl_xor_sync(~0u, sum[r], o);
                sq[r]  += __shfl_xor_sync(~0u, sq[r],  o);
            }
        }
        if (lane == 0) {
#pragma unroll
            for (int r = 0; r < R1; r++) { red[0][r][wid] = sum[r]; red[1][r][wid] = sq[r]; }
        }
        __syncthreads();

        const float4 wv = ((const float4*)lnw)[tid];
        const float4 bv = ((const float4*)lnb)[tid];
#pragma unroll
        for (int r = 0; r < R1; r++) {
            float s = 0.f, q = 0.f;
#pragma unroll
            for (int w = 0; w < 8; w++) { s += red[0][r][w]; q += red[1][r][w]; }
            const float mu   = s * (1.0f / C_S);
            const float var  = q * (1.0f / C_S) - mu * mu;
            const float rstd = rsqrtf(var + 1e-5f);
            float4 sv;
            sv.x = (xv[r].x - mu) * rstd * wv.x + bv.x;
            sv.y = (xv[r].y - mu) * rstd * wv.y + bv.y;
            sv.z = (xv[r].z - mu) * rstd * wv.z + bv.z;
            sv.w = (xv[r].w - mu) * rstd * wv.w + bv.w;
            s4[r][tid] = sv;
        }
    }
    __syncthreads();

    // ---- projection: warp w computes local d = w*4 .. w*4+3 for 8 rows ----
#pragma unroll
    for (int rr = 0; rr < 4; rr++) {
        const int dl = wid * 4 + rr;
        const int dg = h * DD + dl;
        const float4* wr = (const float4*)(pw + (size_t)dg * C_S);
        float acc[R1];
#pragma unroll
        for (int r = 0; r < R1; r++) acc[r] = 0.f;
        for (int c = lane; c < C_S / 4; c += 32) {
            const float4 w4 = wr[c];
#pragma unroll
            for (int r = 0; r < R1; r++) {
                const float4 v = s4[r][c];
                acc[r] = fmaf(v.x, w4.x, fmaf(v.y, w4.y,
                         fmaf(v.z, w4.z, fmaf(v.w, w4.w, acc[r]))));
            }
        }
#pragma unroll
        for (int o = 16; o; o >>= 1) {
#pragma unroll
            for (int r = 0; r < R1; r++) acc[r] += __shfl_xor_sync(~0u, acc[r], o);
        }
        if (lane == 0) {
            const float pbd = pb[dg];
#pragma unroll
            for (int r = 0; r < R1; r++) qk[r][dl] = acc[r] + pbd;
        }
    }
    __syncthreads();

    // ---- write q or k ----
    {
        const int r = tid >> 5, v = tid & 31;
        if (h == 0) g_q[(row0 + r) * DD + v] = qk[r][v];
        else        g_k[(row0 + r) * DD + v] = qk[r][v];
    }

    // ---- Ak (k half only) via padded W2 table in reused s4 space ----
    if (h == 1) {
        float* ow2s = (float*)s4;
        for (int it = tid; it < CZ * DD; it += 256) {
            const int z = it >> 5, d = it & 31;
            ow2s[z * (DD + 1) + d] = ow[z * (2 * DD) + DD + d];
        }
        __syncthreads();
#pragma unroll
        for (int hh = 0; hh < 4; hh++) {
            const int idx = tid + 256 * hh;
            const int r = idx >> 7, z = idx & 127;
            float acc = 0.f;
#pragma unroll
            for (int d = 0; d < DD; d++)
                acc = fmaf(qk[r][d], ow2s[z * (DD + 1) + d], acc);
            g_Ak[(row0 + r) * CZ + z] = acc;
        }
    }
}

// ---------------------------------------------------------------------------
// Phase 2: fp16 m16n8k16 mma (M=z, N=j), fp32 accum, SW128 staging + TMA store.
// 3 CTAs/SM: <=85 regs, 66.5KB smem (2 buffers, f16x2 k table).
// ---------------------------------------------------------------------------
extern __shared__ char smem_dyn[];

__global__ __launch_bounds__(256, 3) void phase2_kernel(
    const __grid_constant__ CUtensorMap tmap,
    const float* __restrict__ ow, const float* __restrict__ ob)
{
    unsigned* ksh = (unsigned*)(smem_dyn + KSH_OFF);   // [16 i][16 d-pairs] f16x2
    unsigned* qsh = (unsigned*)smem_dyn;               // [64 j][20] pairs (temp in buf0)

    uint32_t smem_u32;
    asm("{ .reg .u64 t; cvta.to.shared.u64 t, %1; cvt.u32.u64 %0, t; }"
        : "=r"(smem_u32) : "l"(smem_dyn));

    const int tid  = threadIdx.x;
    const int lane = tid & 31;
    const int wid  = tid >> 5;
    const int l4   = lane & 3;
    const int lg   = lane >> 2;
    const int jbase = blockIdx.x * JT;
    const int ibase = blockIdx.y * I_PER_CTA;

    // ---- one-time staging: q pairs (f16x2, pad-20 rows) and k pairs ----
#pragma unroll
    for (int m = 0; m < 4; m++) {
        const int it = tid + 256 * m;                  // 1024 q pairs
        const int j = it >> 4, p = it & 15;
        const float* qp = g_q + (size_t)(jbase + j) * DD + 2 * p;
        qsh[j * 20 + p] = packh2(qp[0], qp[1]);
    }
    {
        const int ii = tid >> 4, p = tid & 15;         // 256 k pairs
        const float* kp = g_k + (size_t)(ibase + ii) * DD + 2 * p;
        ksh[tid] = packh2(kp[0], kp[1]);
    }

    const int z0 = wid * 16 + lg;            // global z row; +8 for upper

    // ---- W1/W2 as f16x2 fragment pairs, register resident ----
    // w1h[kk][m]: m=0:(z0,d0) 1:(z0+8,d0) 2:(z0,d0+8) 3:(z0+8,d0+8), d0=16kk+2l4
    unsigned w1h[2][4], w2h[2][4];
#pragma unroll
    for (int kk = 0; kk < 2; kk++) {
        const int d0 = 16 * kk + 2 * l4;
        const float* r0 = ow + (size_t)z0 * (2 * DD);
        const float* r1 = ow + (size_t)(z0 + 8) * (2 * DD);
        w1h[kk][0] = packh2(r0[d0],      r0[d0 + 1]);
        w1h[kk][1] = packh2(r1[d0],      r1[d0 + 1]);
        w1h[kk][2] = packh2(r0[d0 + 8],  r0[d0 + 9]);
        w1h[kk][3] = packh2(r1[d0 + 8],  r1[d0 + 9]);
        w2h[kk][0] = packh2(r0[DD + d0],     r0[DD + d0 + 1]);
        w2h[kk][1] = packh2(r1[DD + d0],     r1[DD + d0 + 1]);
        w2h[kk][2] = packh2(r0[DD + d0 + 8], r0[DD + d0 + 9]);
        w2h[kk][3] = packh2(r1[DD + d0 + 8], r1[DD + d0 + 9]);
    }
    const float ob0 = ob[z0];
    const float ob1 = ob[z0 + 8];

    __syncthreads();   // qsh/ksh staged

    // ---- q B fragments: bq[n][0..3] = {kk0 b0, kk0 b1, kk1 b0, kk1 b1} ----
    unsigned bq[8][4];
#pragma unroll
    for (int n = 0; n < 8; n++) {
        const unsigned* qrow = qsh + (8 * n + lg) * 20;
        bq[n][0] = qrow[l4];
        bq[n][1] = qrow[l4 + 4];
        bq[n][2] = qrow[l4 + 8];
        bq[n][3] = qrow[l4 + 12];
    }
    __syncthreads();   // qsh reads done; buf0 may be overwritten

    // staging offsets (same conflict-free SW128 pattern as before)
    const uint32_t p0 = swz((uint32_t)(2 * l4) * 512 + (uint32_t)z0 * 4);
    const uint32_t p1 = p0 ^ 0x240;          // j+1
    const uint32_t p2 = p0 ^ 32;             // z0+8
    const uint32_t p3 = p0 ^ 0x260;          // j+1, z0+8

    const float* akp = g_Ak + (size_t)ibase * CZ + z0;

#pragma unroll 1
    for (int ii = 0; ii < I_PER_CTA; ii++) {
        char* stg = smem_dyn + (ii & 1) * BUFB;

        // prefetch bias early (L2-resident table)
        const float bias0 = ob0 - __ldg(akp + ii * CZ);
        const float bias1 = ob1 - __ldg(akp + ii * CZ + 8);

        // build Ghat A fragments: 8 HFMA2 from f16x2 k pairs (broadcast LDS)
        unsigned afr[2][4];
        {
            const unsigned* kp = ksh + ii * 16;
            const unsigned k00 = kp[l4],      k01 = kp[l4 + 4];
            const unsigned k10 = kp[l4 + 8],  k11 = kp[l4 + 12];
            afr[0][0] = hfma2u(k00, w1h[0][0], w2h[0][0]);
            afr[0][1] = hfma2u(k00, w1h[0][1], w2h[0][1]);
            afr[0][2] = hfma2u(k01, w1h[0][2], w2h[0][2]);
            afr[0][3] = hfma2u(k01, w1h[0][3], w2h[0][3]);
            afr[1][0] = hfma2u(k10, w1h[1][0], w2h[1][0]);
            afr[1][1] = hfma2u(k10, w1h[1][1], w2h[1][1]);
            afr[1][2] = hfma2u(k11, w1h[1][2], w2h[1][2]);
            afr[1][3] = hfma2u(k11, w1h[1][3], w2h[1][3]);
        }

#pragma unroll
        for (int n = 0; n < 8; n++) {
            float c0 = bias0, c1 = bias0, c2 = bias1, c3 = bias1;
#pragma unroll
            for (int kk = 0; kk < 2; kk++) {
                asm volatile(
                    "mma.sync.aligned.m16n8k16.row.col.f32.f16.f16.f32 "
                    "{%0,%1,%2,%3},{%4,%5,%6,%7},{%8,%9},{%0,%1,%2,%3};"
                    : "+f"(c0), "+f"(c1), "+f"(c2), "+f"(c3)
                    : "r"(afr[kk][0]), "r"(afr[kk][1]), "r"(afr[kk][2]), "r"(afr[kk][3]),
                      "r"(bq[n][2 * kk]), "r"(bq[n][2 * kk + 1]));
            }
            const uint32_t nb = (uint32_t)(n << 12);   // j += 8 -> +4096B
            *(float*)(stg + p0 + nb) = c0;
            *(float*)(stg + p1 + nb) = c1;
            *(float*)(stg + p2 + nb) = c2;
            *(float*)(stg + p3 + nb) = c3;
        }

        asm volatile("fence.proxy.async.shared::cta;" ::: "memory");
        __syncthreads();   // all STS for this i visible

        if (tid == 0) {
            const uint32_t sbase = smem_u32 + (ii & 1) * BUFB;
            const int row = (ibase + ii) * L_SEQ + jbase;
            asm volatile(
                "cp.async.bulk.tensor.3d.global.shared::cta.tile.bulk_group "
                "[%0, {%1, %2, %3}], [%4];"
                :: "l"(&tmap), "r"(0), "r"(0), "r"(row), "r"(sbase) : "memory");
            asm volatile("cp.async.bulk.commit_group;" ::: "memory");
            // <=1 group pending: the other buffer is free for ii+1
            asm volatile("cp.async.bulk.wait_group.read 1;" ::: "memory");
        }
        __syncthreads();
    }

    if (tid == 0)
        asm volatile("cp.async.bulk.wait_group 0;" ::: "memory");
}

// ---------------------------------------------------------------------------
typedef CUresult (*EncodeFn)(
    CUtensorMap*, CUtensorMapDataType, cuuint32_t, void*,
    const cuuint64_t*, const cuuint64_t*, const cuuint32_t*, const cuuint32_t*,
    CUtensorMapInterleave, CUtensorMapSwizzle, CUtensorMapL2promotion,
    CUtensorMapFloatOOBfill);

extern "C" void kernel_launch(void* const* d_in, const int* in_sizes, int n_in,
                              void* d_out, int out_size)
{
    const float* x   = (const float*)d_in[0];
    const float* lnw = (const float*)d_in[1];
    const float* lnb = (const float*)d_in[2];
    const float* pw  = (const float*)d_in[3];
    const float* pb  = (const float*)d_in[4];
    const float* ow  = (const float*)d_in[5];
    const float* ob  = (const float*)d_in[6];

    // Output viewed as [row = i*L+j : 1M][chunk : 4][32 f32]; one 32KB box/tile.
    CUtensorMap tmap;
    {
        void* fn = nullptr;
        cudaDriverEntryPointQueryResult qr;
        cudaGetDriverEntryPoint("cuTensorMapEncodeTiled", &fn,
                                cudaEnableDefault, &qr);
        EncodeFn enc = (EncodeFn)fn;
        cuuint64_t dims[3]    = {32, 4, (cuuint64_t)L_SEQ * L_SEQ};
        cuuint64_t strides[2] = {128, 512};          // bytes
        cuuint32_t box[3]     = {32, 4, JT};
        cuuint32_t es[3]      = {1, 1, 1};
        enc(&tmap, CU_TENSOR_MAP_DATA_TYPE_FLOAT32, 3, d_out,
            dims, strides, box, es,
            CU_TENSOR_MAP_INTERLEAVE_NONE, CU_TENSOR_MAP_SWIZZLE_128B,
            CU_TENSOR_MAP_L2_PROMOTION_NONE, CU_TENSOR_MAP_FLOAT_OOB_FILL_NONE);
    }

    cudaFuncSetAttribute(phase2_kernel,
                         cudaFuncAttributeMaxDynamicSharedMemorySize, SMEM2_BYTES);

    phase1_kernel<<<dim3(L_SEQ / R1, 2), 256>>>(x, lnw, lnb, pw, pb, ow);
    phase2_kernel<<<dim3(L_SEQ / JT, L_SEQ / I_PER_CTA), 256, SMEM2_BYTES>>>(
        tmap, ow, ob);
}